// round 16
// baseline (speedup 1.0000x reference)
#include <cuda_runtime.h>

// Problem constants
#define B_   64
#define C_   256        // = D (embedding dim)
#define HW_  1024       // 32*32
#define N_   65536      // B*HW tokens
#define K_   1024       // codebook size
#define D_   256
#define ZQ_ELEMS 16777216   // B*C*HW
#define ARG_BLOCKS 512      // 8 x 64 argmin blocks (loss partials)
#define DC   32             // depth chunk: 128 double-buffered stages
#define EROWF 72            // E tile row stride in floats (STS+LDS conflict-free)

typedef unsigned long long ull;

// Scratch (device globals: allocation-free rule)
__device__ float g_e2[K_];
__device__ float g_partial[ARG_BLOCKS];
__device__ int   g_ticket;

// Packed fp32x2 FMA (Blackwell): acc = a*b + acc elementwise on the 2 lanes.
#define FMA2(acc, a, b) asm("fma.rn.f32x2 %0, %1, %2, %0;" : "+l"(acc) : "l"(a), "l"(b))

static __device__ __forceinline__ ull dup2(float x) {
    unsigned u = __float_as_uint(x);
    return ((ull)u << 32) | (ull)u;
}
static __device__ __forceinline__ float lo_f(ull v) {
    return __uint_as_float((unsigned)(v & 0xffffffffull));
}
static __device__ __forceinline__ float hi_f(ull v) {
    return __uint_as_float((unsigned)(v >> 32));
}

// ---------------------------------------------------------------------------
// e2[k]: per-row sequential fp32 chain (bit-exact order: c=0..255,
// s = fadd(s, fmul(v,v))). 32 blocks x 32 rows, smem-staged coalesced.
// Also resets the fused-loss ticket.
// ---------------------------------------------------------------------------
__global__ __launch_bounds__(256) void e2_kernel(const float* __restrict__ E) {
    __shared__ float tile[32][257];
    const int tid = threadIdx.x;
    if (blockIdx.x == 0 && tid == 0) g_ticket = 0;
    const int r0 = blockIdx.x * 32;

    for (int u = tid; u < 32 * 64; u += 256) {
        int r = u >> 6, c4 = u & 63;
        float4 v = *(const float4*)(E + (size_t)(r0 + r) * D_ + c4 * 4);
        tile[r][c4 * 4 + 0] = v.x; tile[r][c4 * 4 + 1] = v.y;
        tile[r][c4 * 4 + 2] = v.z; tile[r][c4 * 4 + 3] = v.w;
    }
    __syncthreads();

    if (tid < 32) {
        float s = 0.0f;
#pragma unroll 8
        for (int c = 0; c < D_; ++c) {
            float v = tile[tid][c];
            s = __fadd_rn(s, __fmul_rn(v, v));
        }
        g_e2[r0 + tid] = s;
    }
}

// ---------------------------------------------------------------------------
// Argmin + fused gather/loss. grid = (8, 64), 256 threads.
// Mainloop: DC=32 double-buffered; E tile now stored as PLAIN floats
// (row stride 72: STS pattern (r*8+c) mod 32 all-unique, LDS.128 reads are
// 8x16B contiguous with 4-lane broadcast). The packed {e,e} FMA operands are
// built in registers (alu-pipe MOVs) - cuts LDS instructions 4 -> 3 per dd
// and halves E smem bytes. Arithmetic identical -> bit-exact.
// ---------------------------------------------------------------------------
__global__ __launch_bounds__(256, 2) void argmin_kernel(
    const float* __restrict__ z, const float* __restrict__ E,
    float* __restrict__ out, int out_size)
{
    extern __shared__ __align__(16) float dyn[];
    float* Ebuf = dyn;                              // [2][DC][EROWF] plain floats
    float* Zbuf = dyn + 2 * DC * EROWF;             // [2][DC][132]
    __shared__ float e2s[K_];
    __shared__ float z2s[128];
    __shared__ int   idxs[128];
    __shared__ int   is_last;

    const int tid  = threadIdx.x;
    const int lane = tid & 31, warp = tid >> 5;
    const int ky = ((warp & 1) << 3) | (lane >> 2);   // 0..15 (4 k each)
    const int tx = ((warp >> 1) << 2) | (lane & 3);   // 0..15 (8 t each)
    const int b = blockIdx.y;
    const int tbase = blockIdx.x * 128;
    const float* zb = z + (size_t)b * (C_ * HW_);

    const int ekl = tid >> 2, edq = tid & 3;        // E loader: 64k x (2x4 d-quads)
    const int zr  = tid >> 5, zc = (tid & 31) * 4;  // Z loader: 4 rows x 128t

    // --- prologue: stage-0 tile loads into buffer 0 (kc=0, d0=0) ---
    {
        float4 ev0 = *(const float4*)(E + (size_t)ekl * D_ + edq * 4);
        float4 ev1 = *(const float4*)(E + (size_t)ekl * D_ + 16 + edq * 4);
        Ebuf[(edq * 4 + 0) * EROWF + ekl] = ev0.x;
        Ebuf[(edq * 4 + 1) * EROWF + ekl] = ev0.y;
        Ebuf[(edq * 4 + 2) * EROWF + ekl] = ev0.z;
        Ebuf[(edq * 4 + 3) * EROWF + ekl] = ev0.w;
        Ebuf[(16 + edq * 4 + 0) * EROWF + ekl] = ev1.x;
        Ebuf[(16 + edq * 4 + 1) * EROWF + ekl] = ev1.y;
        Ebuf[(16 + edq * 4 + 2) * EROWF + ekl] = ev1.z;
        Ebuf[(16 + edq * 4 + 3) * EROWF + ekl] = ev1.w;
#pragma unroll
        for (int r = 0; r < 4; ++r) {
            float4 zv = *(const float4*)(zb + (size_t)(zr + r * 8) * HW_ + tbase + zc);
            *(float4*)&Zbuf[(zr + r * 8) * 132 + zc] = zv;
        }
    }

    // --- e2s copy + in-block z2 (identical sequential order -> bit-exact) ---
    if (tid >= 128) {
        for (int j = tid - 128; j < K_; j += 128) e2s[j] = g_e2[j];
    } else {
        const float* pz = zb + tbase + tid;
        float s = 0.0f;
#pragma unroll 8
        for (int c = 0; c < C_; ++c) {
            float v = pz[(size_t)c * HW_];
            s = __fadd_rn(s, __fmul_rn(v, v));
        }
        z2s[tid] = s;
    }

    float bestv[8];
    int   besti[8];
#pragma unroll
    for (int j = 0; j < 8; ++j) { bestv[j] = 3.4e38f; besti[j] = 0; }

    for (int kc = 0; kc < 16; ++kc) {
        const int kbase = kc * 64;
        ull acc[4][4];
#pragma unroll
        for (int i = 0; i < 4; ++i)
#pragma unroll
            for (int j = 0; j < 4; ++j) acc[i][j] = 0ull;

        for (int dc = 0; dc < 8; ++dc) {
            const int s = kc * 8 + dc;
            float* Ecur = Ebuf + (s & 1) * (DC * EROWF);
            float* Zcur = Zbuf + (s & 1) * (DC * 132);
            float* Enxt = Ebuf + ((s + 1) & 1) * (DC * EROWF);
            float* Znxt = Zbuf + ((s + 1) & 1) * (DC * 132);

            __syncthreads();   // cur visible; prior reads of nxt done

            // prefetch next stage into registers (hidden under compute)
            const int sn = s + 1;
            const bool pf = (sn < 128);
            float4 ev0, ev1, zv0, zv1, zv2, zv3;
            if (pf) {
                const int nkc = sn >> 3, nd0 = (sn & 7) * 32;
                const float* ep = E + (size_t)(nkc * 64 + ekl) * D_ + nd0 + edq * 4;
                ev0 = *(const float4*)ep;
                ev1 = *(const float4*)(ep + 16);
                const float* zp = zb + (size_t)(nd0 + zr) * HW_ + tbase + zc;
                zv0 = *(const float4*)zp;
                zv1 = *(const float4*)(zp + (size_t)8 * HW_);
                zv2 = *(const float4*)(zp + (size_t)16 * HW_);
                zv3 = *(const float4*)(zp + (size_t)24 * HW_);
            }

#pragma unroll
            for (int dd = 0; dd < DC; ++dd) {
                const float* Er = Ecur + dd * EROWF;
                const ull* Zr2 = (const ull*)(Zcur + dd * 132);
                float4 ef = *(const float4*)(Er + ky * 4);   // 4 k, plain floats
                ull e0 = dup2(ef.x), e1 = dup2(ef.y);        // packed {e,e} in regs
                ull e2 = dup2(ef.z), e3 = dup2(ef.w);
                ulonglong2 z01 = *(const ulonglong2*)(Zr2 + tx * 4);
                ulonglong2 z23 = *(const ulonglong2*)(Zr2 + tx * 4 + 2);
                FMA2(acc[0][0], e0, z01.x); FMA2(acc[0][1], e0, z01.y);
                FMA2(acc[0][2], e0, z23.x); FMA2(acc[0][3], e0, z23.y);
                FMA2(acc[1][0], e1, z01.x); FMA2(acc[1][1], e1, z01.y);
                FMA2(acc[1][2], e1, z23.x); FMA2(acc[1][3], e1, z23.y);
                FMA2(acc[2][0], e2, z01.x); FMA2(acc[2][1], e2, z01.y);
                FMA2(acc[2][2], e2, z23.x); FMA2(acc[2][3], e2, z23.y);
                FMA2(acc[3][0], e3, z01.x); FMA2(acc[3][1], e3, z01.y);
                FMA2(acc[3][2], e3, z23.x); FMA2(acc[3][3], e3, z23.y);
            }

            if (pf) {
                Enxt[(edq * 4 + 0) * EROWF + ekl] = ev0.x;
                Enxt[(edq * 4 + 1) * EROWF + ekl] = ev0.y;
                Enxt[(edq * 4 + 2) * EROWF + ekl] = ev0.z;
                Enxt[(edq * 4 + 3) * EROWF + ekl] = ev0.w;
                Enxt[(16 + edq * 4 + 0) * EROWF + ekl] = ev1.x;
                Enxt[(16 + edq * 4 + 1) * EROWF + ekl] = ev1.y;
                Enxt[(16 + edq * 4 + 2) * EROWF + ekl] = ev1.z;
                Enxt[(16 + edq * 4 + 3) * EROWF + ekl] = ev1.w;
                *(float4*)&Znxt[(zr +  0) * 132 + zc] = zv0;
                *(float4*)&Znxt[(zr +  8) * 132 + zc] = zv1;
                *(float4*)&Znxt[(zr + 16) * 132 + zc] = zv2;
                *(float4*)&Znxt[(zr + 24) * 132 + zc] = zv3;
            }
        }

        // distances + running argmin (reference rounding tree, no contraction)
#pragma unroll
        for (int i = 0; i < 4; ++i) {
            const int k = kbase + ky * 4 + i;
            const float e2k = e2s[k];
#pragma unroll
            for (int j = 0; j < 4; ++j) {
                const int t0 = tx * 8 + j * 2;
                float a0 = lo_f(acc[i][j]), a1 = hi_f(acc[i][j]);
                float d0 = __fsub_rn(__fadd_rn(z2s[t0], e2k),
                                     __fmul_rn(2.0f, a0));
                float d1 = __fsub_rn(__fadd_rn(z2s[t0 + 1], e2k),
                                     __fmul_rn(2.0f, a1));
                if (d0 < bestv[j * 2])     { bestv[j * 2]     = d0; besti[j * 2]     = k; }
                if (d1 < bestv[j * 2 + 1]) { bestv[j * 2 + 1] = d1; besti[j * 2 + 1] = k; }
            }
        }
    }

    // --- cross-ky reduction (reuse dynamic tile smem) ---
    __syncthreads();
    float* rv = dyn;                      // 16 x 128
    int*   ri = (int*)(rv + 16 * 128);
#pragma unroll
    for (int j = 0; j < 8; ++j) {
        rv[ky * 128 + tx * 8 + j] = bestv[j];
        ri[ky * 128 + tx * 8 + j] = besti[j];
    }
    __syncthreads();
    if (tid < 128) {
        float bv = rv[tid];
        int   bi = ri[tid];
#pragma unroll
        for (int r = 1; r < 16; ++r) {
            float v = rv[r * 128 + tid]; int ii = ri[r * 128 + tid];
            if (v < bv || (v == bv && ii < bi)) { bv = v; bi = ii; }
        }
        idxs[tid] = bi;
        const int n = b * HW_ + tbase + tid;
        if (out_size >= ZQ_ELEMS + 1 + N_)
            out[(size_t)ZQ_ELEMS + 1 + n] = (float)bi;
    }

    // =====================================================================
    // Fused gather + loss partial. Two 64-token halves; selected E rows
    // staged in dyn (64 x 257 floats = 65792 B, the dyn allocation size).
    // z_q = fl(z + fl(e - z)) (same rounding as before).
    // =====================================================================
    float* Eg = dyn;
    float part = 0.0f;
    const int q  = tid & 15;    // token quad within the 64-half
    const int cw = tid >> 4;    // channel start 0..15
#pragma unroll 1
    for (int h = 0; h < 2; ++h) {
        __syncthreads();   // prior phase's reads of dyn complete
        for (int u = tid; u < 64 * 64; u += 256) {   // 64 rows x 64 float4
            int i = u >> 6, c4 = u & 63;
            float4 v = *(const float4*)(E + (size_t)idxs[h * 64 + i] * D_ + c4 * 4);
            Eg[i * 257 + c4 * 4 + 0] = v.x; Eg[i * 257 + c4 * 4 + 1] = v.y;
            Eg[i * 257 + c4 * 4 + 2] = v.z; Eg[i * 257 + c4 * 4 + 3] = v.w;
        }
        __syncthreads();

        const float* zrow = zb + tbase + h * 64 + q * 4;
        float*       orow = out + (size_t)b * (C_ * HW_) + tbase + h * 64 + q * 4;
#pragma unroll 4
        for (int c = cw; c < C_; c += 16) {
            float4 zv = *(const float4*)(zrow + (size_t)c * HW_);
            float d0 = __fsub_rn(Eg[(q * 4 + 0) * 257 + c], zv.x);
            float d1 = __fsub_rn(Eg[(q * 4 + 1) * 257 + c], zv.y);
            float d2 = __fsub_rn(Eg[(q * 4 + 2) * 257 + c], zv.z);
            float d3 = __fsub_rn(Eg[(q * 4 + 3) * 257 + c], zv.w);
            float4 ov;
            ov.x = __fadd_rn(zv.x, d0);
            ov.y = __fadd_rn(zv.y, d1);
            ov.z = __fadd_rn(zv.z, d2);
            ov.w = __fadd_rn(zv.w, d3);
            *(float4*)(orow + (size_t)c * HW_) = ov;
            part = __fmaf_rn(d0, d0, part);
            part = __fmaf_rn(d1, d1, part);
            part = __fmaf_rn(d2, d2, part);
            part = __fmaf_rn(d3, d3, part);
        }
    }

    // block loss partial -> g_partial; last-of-512 reduces (fixed order)
    __syncthreads();
    float* red = dyn;
    red[tid] = part;
    __syncthreads();
    for (int s = 128; s > 0; s >>= 1) {
        if (tid < s) red[tid] += red[tid + s];
        __syncthreads();
    }
    const int bid = blockIdx.y * 8 + blockIdx.x;
    if (tid == 0) {
        g_partial[bid] = red[0];
        __threadfence();
        int t = atomicAdd(&g_ticket, 1);
        is_last = (t == ARG_BLOCKS - 1) ? 1 : 0;
    }
    __syncthreads();

    if (is_last) {
        float s = 0.0f;
        for (int i = tid; i < ARG_BLOCKS; i += 256) s += g_partial[i];
        red[tid] = s;
        __syncthreads();
        for (int st = 128; st > 0; st >>= 1) {
            if (tid < st) red[tid] += red[tid + st];
            __syncthreads();
        }
        if (tid == 0 && out_size > ZQ_ELEMS) {
            float m = red[0] / 16777216.0f;
            out[ZQ_ELEMS] = __fadd_rn(m, __fmul_rn(0.25f, m));
        }
    }
}

// dyn must fit: tiles (2*DC*EROWF + 2*DC*132 floats = 52224 B) AND the
// gather staging (64*257 floats = 65792 B) -> 65792 B.
#define ARGMIN_DYN_BYTES 65792

extern "C" void kernel_launch(void* const* d_in, const int* in_sizes, int n_in,
                              void* d_out, int out_size) {
    const float* z = (const float*)d_in[0];   // [64,256,32,32]
    const float* E = (const float*)d_in[1];   // [1024,256]
    float* out = (float*)d_out;

    // Host-side attribute set: runs during capture setup only, not in graph.
    cudaFuncSetAttribute(argmin_kernel,
                         cudaFuncAttributeMaxDynamicSharedMemorySize,
                         ARGMIN_DYN_BYTES);

    e2_kernel<<<K_ / 32, 256>>>(E);
    dim3 grid(8, 64);
    argmin_kernel<<<grid, 256, ARGMIN_DYN_BYTES>>>(z, E, out, out_size);
}

// round 17
// speedup vs baseline: 1.6300x; 1.6300x over previous
#include <cuda_runtime.h>

// Problem constants
#define B_   64
#define C_   256        // = D (embedding dim)
#define HW_  1024       // 32*32
#define N_   65536      // B*HW tokens
#define K_   1024       // codebook size
#define D_   256
#define ZQ_ELEMS 16777216   // B*C*HW
#define ARG_BLOCKS 512      // 8 x 64 argmin blocks (loss partials)
#define DC   32             // depth chunk: 128 double-buffered stages
#define EROWF 72            // E tile row stride in floats (STS+LDS conflict-free)

typedef unsigned long long ull;

// Scratch (device globals: allocation-free rule)
__device__ float g_e2[K_];
__device__ float g_partial[ARG_BLOCKS];
__device__ int   g_ticket;

// Packed fp32x2 FMA (Blackwell): acc = a*b + acc elementwise on the 2 lanes.
#define FMA2(acc, a, b) asm("fma.rn.f32x2 %0, %1, %2, %0;" : "+l"(acc) : "l"(a), "l"(b))

static __device__ __forceinline__ ull dup2(float x) {
    unsigned u = __float_as_uint(x);
    return ((ull)u << 32) | (ull)u;
}
static __device__ __forceinline__ float lo_f(ull v) {
    return __uint_as_float((unsigned)(v & 0xffffffffull));
}
static __device__ __forceinline__ float hi_f(ull v) {
    return __uint_as_float((unsigned)(v >> 32));
}

// ---------------------------------------------------------------------------
// e2[k]: per-row sequential fp32 chain (bit-exact order: c=0..255,
// s = fadd(s, fmul(v,v))). 32 blocks x 32 rows, smem-staged coalesced.
// Also resets the fused-loss ticket.
// ---------------------------------------------------------------------------
__global__ __launch_bounds__(256) void e2_kernel(const float* __restrict__ E) {
    __shared__ float tile[32][257];
    const int tid = threadIdx.x;
    if (blockIdx.x == 0 && tid == 0) g_ticket = 0;
    const int r0 = blockIdx.x * 32;

    for (int u = tid; u < 32 * 64; u += 256) {
        int r = u >> 6, c4 = u & 63;
        float4 v = *(const float4*)(E + (size_t)(r0 + r) * D_ + c4 * 4);
        tile[r][c4 * 4 + 0] = v.x; tile[r][c4 * 4 + 1] = v.y;
        tile[r][c4 * 4 + 2] = v.z; tile[r][c4 * 4 + 3] = v.w;
    }
    __syncthreads();

    if (tid < 32) {
        float s = 0.0f;
#pragma unroll 8
        for (int c = 0; c < D_; ++c) {
            float v = tile[tid][c];
            s = __fadd_rn(s, __fmul_rn(v, v));
        }
        g_e2[r0 + tid] = s;
    }
}

// ---------------------------------------------------------------------------
// Argmin + fused gather/loss. grid = (8, 64), 256 threads.
// Mainloop: DC=32 double-buffered; E tile stored as PLAIN floats
// (row stride 72: STS pattern (r*8+c) mod 32 all-unique, LDS.128 reads are
// 8x16B contiguous with 4-lane broadcast). Packed {e,e} FMA operands built
// in registers - 3 LDS.128 per dd, halved E smem bytes. Bit-exact chain.
// ---------------------------------------------------------------------------
__global__ __launch_bounds__(256, 2) void argmin_kernel(
    const float* __restrict__ z, const float* __restrict__ E,
    float* __restrict__ out, int out_size)
{
    extern __shared__ __align__(16) float dyn[];
    float* Ebuf = dyn;                              // [2][DC][EROWF] plain floats
    float* Zbuf = dyn + 2 * DC * EROWF;             // [2][DC][132]
    __shared__ float e2s[K_];
    __shared__ float z2s[128];
    __shared__ int   idxs[128];
    __shared__ int   is_last;

    const int tid  = threadIdx.x;
    const int lane = tid & 31, warp = tid >> 5;
    const int ky = ((warp & 1) << 3) | (lane >> 2);   // 0..15 (4 k each)
    const int tx = ((warp >> 1) << 2) | (lane & 3);   // 0..15 (8 t each)
    const int b = blockIdx.y;
    const int tbase = blockIdx.x * 128;
    const float* zb = z + (size_t)b * (C_ * HW_);

    const int ekl = tid >> 2, edq = tid & 3;        // E loader: 64k x (2x4 d-quads)
    const int zr  = tid >> 5, zc = (tid & 31) * 4;  // Z loader: 4 rows x 128t

    // --- prologue: stage-0 tile loads into buffer 0 (kc=0, d0=0) ---
    {
        float4 ev0 = *(const float4*)(E + (size_t)ekl * D_ + edq * 4);
        float4 ev1 = *(const float4*)(E + (size_t)ekl * D_ + 16 + edq * 4);
        Ebuf[(edq * 4 + 0) * EROWF + ekl] = ev0.x;
        Ebuf[(edq * 4 + 1) * EROWF + ekl] = ev0.y;
        Ebuf[(edq * 4 + 2) * EROWF + ekl] = ev0.z;
        Ebuf[(edq * 4 + 3) * EROWF + ekl] = ev0.w;
        Ebuf[(16 + edq * 4 + 0) * EROWF + ekl] = ev1.x;
        Ebuf[(16 + edq * 4 + 1) * EROWF + ekl] = ev1.y;
        Ebuf[(16 + edq * 4 + 2) * EROWF + ekl] = ev1.z;
        Ebuf[(16 + edq * 4 + 3) * EROWF + ekl] = ev1.w;
#pragma unroll
        for (int r = 0; r < 4; ++r) {
            float4 zv = *(const float4*)(zb + (size_t)(zr + r * 8) * HW_ + tbase + zc);
            *(float4*)&Zbuf[(zr + r * 8) * 132 + zc] = zv;
        }
    }

    // --- e2s copy + in-block z2 (identical sequential order -> bit-exact) ---
    if (tid >= 128) {
        for (int j = tid - 128; j < K_; j += 128) e2s[j] = g_e2[j];
    } else {
        const float* pz = zb + tbase + tid;
        float s = 0.0f;
#pragma unroll 8
        for (int c = 0; c < C_; ++c) {
            float v = pz[(size_t)c * HW_];
            s = __fadd_rn(s, __fmul_rn(v, v));
        }
        z2s[tid] = s;
    }

    float bestv[8];
    int   besti[8];
#pragma unroll
    for (int j = 0; j < 8; ++j) { bestv[j] = 3.4e38f; besti[j] = 0; }

    for (int kc = 0; kc < 16; ++kc) {
        const int kbase = kc * 64;
        ull acc[4][4];
#pragma unroll
        for (int i = 0; i < 4; ++i)
#pragma unroll
            for (int j = 0; j < 4; ++j) acc[i][j] = 0ull;

        for (int dc = 0; dc < 8; ++dc) {
            const int s = kc * 8 + dc;
            float* Ecur = Ebuf + (s & 1) * (DC * EROWF);
            float* Zcur = Zbuf + (s & 1) * (DC * 132);
            float* Enxt = Ebuf + ((s + 1) & 1) * (DC * EROWF);
            float* Znxt = Zbuf + ((s + 1) & 1) * (DC * 132);

            __syncthreads();   // cur visible; prior reads of nxt done

            // prefetch next stage into registers (hidden under compute)
            const int sn = s + 1;
            const bool pf = (sn < 128);
            float4 ev0, ev1, zv0, zv1, zv2, zv3;
            if (pf) {
                const int nkc = sn >> 3, nd0 = (sn & 7) * 32;
                const float* ep = E + (size_t)(nkc * 64 + ekl) * D_ + nd0 + edq * 4;
                ev0 = *(const float4*)ep;
                ev1 = *(const float4*)(ep + 16);
                const float* zp = zb + (size_t)(nd0 + zr) * HW_ + tbase + zc;
                zv0 = *(const float4*)zp;
                zv1 = *(const float4*)(zp + (size_t)8 * HW_);
                zv2 = *(const float4*)(zp + (size_t)16 * HW_);
                zv3 = *(const float4*)(zp + (size_t)24 * HW_);
            }

#pragma unroll
            for (int dd = 0; dd < DC; ++dd) {
                const float* Er = Ecur + dd * EROWF;
                const ull* Zr2 = (const ull*)(Zcur + dd * 132);
                float4 ef = *(const float4*)(Er + ky * 4);   // 4 k, plain floats
                ull e0 = dup2(ef.x), e1 = dup2(ef.y);        // packed {e,e} in regs
                ull e2 = dup2(ef.z), e3 = dup2(ef.w);
                ulonglong2 z01 = *(const ulonglong2*)(Zr2 + tx * 4);
                ulonglong2 z23 = *(const ulonglong2*)(Zr2 + tx * 4 + 2);
                FMA2(acc[0][0], e0, z01.x); FMA2(acc[0][1], e0, z01.y);
                FMA2(acc[0][2], e0, z23.x); FMA2(acc[0][3], e0, z23.y);
                FMA2(acc[1][0], e1, z01.x); FMA2(acc[1][1], e1, z01.y);
                FMA2(acc[1][2], e1, z23.x); FMA2(acc[1][3], e1, z23.y);
                FMA2(acc[2][0], e2, z01.x); FMA2(acc[2][1], e2, z01.y);
                FMA2(acc[2][2], e2, z23.x); FMA2(acc[2][3], e2, z23.y);
                FMA2(acc[3][0], e3, z01.x); FMA2(acc[3][1], e3, z01.y);
                FMA2(acc[3][2], e3, z23.x); FMA2(acc[3][3], e3, z23.y);
            }

            if (pf) {
                Enxt[(edq * 4 + 0) * EROWF + ekl] = ev0.x;
                Enxt[(edq * 4 + 1) * EROWF + ekl] = ev0.y;
                Enxt[(edq * 4 + 2) * EROWF + ekl] = ev0.z;
                Enxt[(edq * 4 + 3) * EROWF + ekl] = ev0.w;
                Enxt[(16 + edq * 4 + 0) * EROWF + ekl] = ev1.x;
                Enxt[(16 + edq * 4 + 1) * EROWF + ekl] = ev1.y;
                Enxt[(16 + edq * 4 + 2) * EROWF + ekl] = ev1.z;
                Enxt[(16 + edq * 4 + 3) * EROWF + ekl] = ev1.w;
                *(float4*)&Znxt[(zr +  0) * 132 + zc] = zv0;
                *(float4*)&Znxt[(zr +  8) * 132 + zc] = zv1;
                *(float4*)&Znxt[(zr + 16) * 132 + zc] = zv2;
                *(float4*)&Znxt[(zr + 24) * 132 + zc] = zv3;
            }
        }

        // distances + running argmin (reference rounding tree, no contraction)
#pragma unroll
        for (int i = 0; i < 4; ++i) {
            const int k = kbase + ky * 4 + i;
            const float e2k = e2s[k];
#pragma unroll
            for (int j = 0; j < 4; ++j) {
                const int t0 = tx * 8 + j * 2;
                float a0 = lo_f(acc[i][j]), a1 = hi_f(acc[i][j]);
                float d0 = __fsub_rn(__fadd_rn(z2s[t0], e2k),
                                     __fmul_rn(2.0f, a0));
                float d1 = __fsub_rn(__fadd_rn(z2s[t0 + 1], e2k),
                                     __fmul_rn(2.0f, a1));
                if (d0 < bestv[j * 2])     { bestv[j * 2]     = d0; besti[j * 2]     = k; }
                if (d1 < bestv[j * 2 + 1]) { bestv[j * 2 + 1] = d1; besti[j * 2 + 1] = k; }
            }
        }
    }

    // --- cross-ky reduction (reuse dynamic tile smem) ---
    __syncthreads();
    float* rv = dyn;                      // 16 x 128
    int*   ri = (int*)(rv + 16 * 128);
#pragma unroll
    for (int j = 0; j < 8; ++j) {
        rv[ky * 128 + tx * 8 + j] = bestv[j];
        ri[ky * 128 + tx * 8 + j] = besti[j];
    }
    __syncthreads();
    if (tid < 128) {
        float bv = rv[tid];
        int   bi = ri[tid];
#pragma unroll
        for (int r = 1; r < 16; ++r) {
            float v = rv[r * 128 + tid]; int ii = ri[r * 128 + tid];
            if (v < bv || (v == bv && ii < bi)) { bv = v; bi = ii; }
        }
        idxs[tid] = bi;
        const int n = b * HW_ + tbase + tid;
        if (out_size >= ZQ_ELEMS + 1 + N_)
            out[(size_t)ZQ_ELEMS + 1 + n] = (float)bi;
    }

    // =====================================================================
    // Fused gather + loss partial. Two 64-token halves; selected E rows
    // staged in dyn (64 x 257 floats = 65792 B, the dyn allocation size).
    // z_q = fl(z + fl(e - z)) (same rounding as before).
    // =====================================================================
    float* Eg = dyn;
    float part = 0.0f;
    const int q  = tid & 15;    // token quad within the 64-half
    const int cw = tid >> 4;    // channel start 0..15
#pragma unroll 1
    for (int h = 0; h < 2; ++h) {
        __syncthreads();   // prior phase's reads of dyn complete
        for (int u = tid; u < 64 * 64; u += 256) {   // 64 rows x 64 float4
            int i = u >> 6, c4 = u & 63;
            float4 v = *(const float4*)(E + (size_t)idxs[h * 64 + i] * D_ + c4 * 4);
            Eg[i * 257 + c4 * 4 + 0] = v.x; Eg[i * 257 + c4 * 4 + 1] = v.y;
            Eg[i * 257 + c4 * 4 + 2] = v.z; Eg[i * 257 + c4 * 4 + 3] = v.w;
        }
        __syncthreads();

        const float* zrow = zb + tbase + h * 64 + q * 4;
        float*       orow = out + (size_t)b * (C_ * HW_) + tbase + h * 64 + q * 4;
#pragma unroll 4
        for (int c = cw; c < C_; c += 16) {
            float4 zv = *(const float4*)(zrow + (size_t)c * HW_);
            float d0 = __fsub_rn(Eg[(q * 4 + 0) * 257 + c], zv.x);
            float d1 = __fsub_rn(Eg[(q * 4 + 1) * 257 + c], zv.y);
            float d2 = __fsub_rn(Eg[(q * 4 + 2) * 257 + c], zv.z);
            float d3 = __fsub_rn(Eg[(q * 4 + 3) * 257 + c], zv.w);
            float4 ov;
            ov.x = __fadd_rn(zv.x, d0);
            ov.y = __fadd_rn(zv.y, d1);
            ov.z = __fadd_rn(zv.z, d2);
            ov.w = __fadd_rn(zv.w, d3);
            *(float4*)(orow + (size_t)c * HW_) = ov;
            part = __fmaf_rn(d0, d0, part);
            part = __fmaf_rn(d1, d1, part);
            part = __fmaf_rn(d2, d2, part);
            part = __fmaf_rn(d3, d3, part);
        }
    }

    // block loss partial -> g_partial; last-of-512 reduces (fixed order)
    __syncthreads();
    float* red = dyn;
    red[tid] = part;
    __syncthreads();
    for (int s = 128; s > 0; s >>= 1) {
        if (tid < s) red[tid] += red[tid + s];
        __syncthreads();
    }
    const int bid = blockIdx.y * 8 + blockIdx.x;
    if (tid == 0) {
        g_partial[bid] = red[0];
        __threadfence();
        int t = atomicAdd(&g_ticket, 1);
        is_last = (t == ARG_BLOCKS - 1) ? 1 : 0;
    }
    __syncthreads();

    if (is_last) {
        float s = 0.0f;
        for (int i = tid; i < ARG_BLOCKS; i += 256) s += g_partial[i];
        red[tid] = s;
        __syncthreads();
        for (int st = 128; st > 0; st >>= 1) {
            if (tid < st) red[tid] += red[tid + st];
            __syncthreads();
        }
        if (tid == 0 && out_size > ZQ_ELEMS) {
            float m = red[0] / 16777216.0f;
            out[ZQ_ELEMS] = __fadd_rn(m, __fmul_rn(0.25f, m));
        }
    }
}

// dyn must fit: tiles (2*DC*EROWF + 2*DC*132 floats = 52224 B) AND the
// gather staging (64*257 floats = 65792 B) -> 65792 B.
#define ARGMIN_DYN_BYTES 65792

extern "C" void kernel_launch(void* const* d_in, const int* in_sizes, int n_in,
                              void* d_out, int out_size) {
    const float* z = (const float*)d_in[0];   // [64,256,32,32]
    const float* E = (const float*)d_in[1];   // [1024,256]
    float* out = (float*)d_out;

    // Host-side attribute set: runs during capture setup only, not in graph.
    cudaFuncSetAttribute(argmin_kernel,
                         cudaFuncAttributeMaxDynamicSharedMemorySize,
                         ARGMIN_DYN_BYTES);

    e2_kernel<<<K_ / 32, 256>>>(E);
    dim3 grid(8, 64);
    argmin_kernel<<<grid, 256, ARGMIN_DYN_BYTES>>>(z, E, out, out_size);
}